// round 7
// baseline (speedup 1.0000x reference)
#include <cuda_runtime.h>
#include <math.h>
#include <stdint.h>

#define B_   4096
#define M_   16
#define C_   1000
#define EMB_ 100
#define EPAD 101
#define K_   1000
#define NL_  4

// output layout (tuple-order concat, fp32)
#define O_POST  0
#define O_CHILD 4096000
#define O_CONF  4096001
#define O_ENS   4096002
#define O_WMS   4096003
#define O_TC    4161539

// scratch
__device__ float g_emb[M_ * EMB_];
__device__ float g_wm [B_ * M_];
__device__ float g_pw [B_ * M_];
__device__ float g_wms[B_ * M_];
__device__ __align__(16) float g_part[B_ * 4];
__device__ unsigned int g_ctr;

__device__ __forceinline__ void cp16(uint32_t d, const void* s, int nbytes) {
    asm volatile("cp.async.cg.shared.global [%0], [%1], 16, %2;\n"
                 :: "r"(d), "l"(s), "r"(nbytes));
}

// ---------------------------------------------------------------------------
// Kernel A: emb[m][e] = relu(model_emb[m,:] . w2[e,:] + b2[e])
// ---------------------------------------------------------------------------
__global__ void k_emb(const float* __restrict__ me, const float* __restrict__ w2,
                      const float* __restrict__ b2) {
    int m = blockIdx.x;
    int wid = threadIdx.x >> 5, lane = threadIdx.x & 31;
    int e = blockIdx.y * 8 + wid;
    if (e >= EMB_) return;
    const float* mer = me + m * K_;
    const float* w2r = w2 + e * K_;
    float acc = 0.f;
    #pragma unroll
    for (int i = 0; i < 32; i++) {
        int k = lane + (i << 5);
        if (k < K_) acc += mer[k] * w2r[k];
    }
    #pragma unroll
    for (int off = 16; off; off >>= 1)
        acc += __shfl_xor_sync(0xffffffffu, acc, off);
    if (lane == 0) g_emb[m * EMB_ + e] = fmaxf(acc + b2[e], 0.f);
}

// resets the completion counter used by k_main's fused final reduce
__global__ void k_dummy() { if (threadIdx.x == 0) g_ctr = 0u; }

// ---------------------------------------------------------------------------
// Kernel B: routing. 256 blocks x 256 threads (8 warps), 2 rows/warp,
// 2 CTAs/SM -> 16 warps/SM for SHFL-latency hiding.
// w1 double-buffered via cp.async.
// ---------------------------------------------------------------------------
#define CE_ 4

__global__ __launch_bounds__(256, 2)
void k_route(const float* __restrict__ x_in, const float* __restrict__ w1,
             const float* __restrict__ b1, const float* __restrict__ w3,
             const float* __restrict__ b3, float* __restrict__ out) {
    __shared__ __align__(16) float w_s[2][CE_ * 1024];   // 32 KB
    __shared__ float emb_s[M_ * EPAD];
    __shared__ float b1_s[EMB_];
    __shared__ float w3_s[M_ * M_];
    __shared__ float b3_s[M_];
    __shared__ float wtmp[16 * M_];

    int tid = threadIdx.x, wid = tid >> 5, lane = tid & 31;
    int base = blockIdx.x * 16;
    int m = lane & 15, h = lane >> 4;

    for (int i = tid; i < M_ * EMB_; i += 256) {
        int mm = i / EMB_, ee = i - mm * EMB_;
        emb_s[mm * EPAD + ee] = g_emb[i];
    }
    if (tid < EMB_) b1_s[tid] = b1[tid];
    if (tid < M_ * M_) w3_s[tid] = w3[tid];
    if (tid < M_) b3_s[tid] = b3[tid];

    // x preload: 2 rows per warp, layout k = 4*lane + 128*i
    float4 xr[2][8];
    #pragma unroll
    for (int r = 0; r < 2; r++) {
        const float* xp = x_in + (size_t)(base + 2 * wid + r) * K_;
        #pragma unroll
        for (int i = 0; i < 8; i++) {
            int k = 4 * lane + 128 * i;
            xr[r][i] = (k < K_) ? *(const float4*)(xp + k)
                                : make_float4(0.f, 0.f, 0.f, 0.f);
        }
    }

    uint32_t wb0 = (uint32_t)__cvta_generic_to_shared(&w_s[0][0]);
    uint32_t wb1 = (uint32_t)__cvta_generic_to_shared(&w_s[1][0]);

    #define STAGE(c, wb) do {                                                  \
        int ec_ = (c) * CE_;                                                   \
        _Pragma("unroll")                                                      \
        for (int j_ = 0; j_ < 4; j_++) {                                       \
            int f4_ = j_ * 256 + tid;                                          \
            int el_ = f4_ >> 8, c4_ = f4_ & 255;                               \
            const float* src_ = w1 + (size_t)(ec_ + el_) * K_                  \
                                  + ((c4_ < 250) ? c4_ * 4 : 0);               \
            int nb_ = (c4_ < 250) ? 16 : 0;                                    \
            cp16((wb) + (uint32_t)((el_ * 1024 + c4_ * 4) * 4), src_, nb_);    \
        }                                                                      \
        asm volatile("cp.async.commit_group;\n");                              \
    } while (0)

    STAGE(0, wb0);

    float score0 = 0.f, score1 = 0.f;

    for (int c = 0; c < 25; c++) {
        asm volatile("cp.async.wait_group 0;\n");
        __syncthreads();
        if (c + 1 < 25) STAGE(c + 1, (c & 1) ? wb0 : wb1);
        const float* wbp = w_s[c & 1];

        #pragma unroll
        for (int ep = 0; ep < 2; ep++) {
            const float* w0p = wbp + (2 * ep) * 1024;
            const float* w1p = wbp + (2 * ep + 1) * 1024;
            float a00 = 0, a01 = 0, a10 = 0, a11 = 0;
            #pragma unroll
            for (int i = 0; i < 8; i++) {
                int k = 4 * lane + 128 * i;
                float4 wa = *(const float4*)(w0p + k);
                float4 wc = *(const float4*)(w1p + k);
                float4 q;
                q = xr[0][i];
                a00 += wa.x*q.x + wa.y*q.y + wa.z*q.z + wa.w*q.w;
                a10 += wc.x*q.x + wc.y*q.y + wc.z*q.z + wc.w*q.w;
                q = xr[1][i];
                a01 += wa.x*q.x + wa.y*q.y + wa.z*q.z + wa.w*q.w;
                a11 += wc.x*q.x + wc.y*q.y + wc.z*q.z + wc.w*q.w;
            }
            #pragma unroll
            for (int off = 16; off; off >>= 1) {
                a00 += __shfl_xor_sync(0xffffffffu, a00, off);
                a01 += __shfl_xor_sync(0xffffffffu, a01, off);
                a10 += __shfl_xor_sync(0xffffffffu, a10, off);
                a11 += __shfl_xor_sync(0xffffffffu, a11, off);
            }
            int elh = c * CE_ + 2 * ep + h;
            float bias = b1_s[elh];
            float em   = emb_s[m * EPAD + elh];
            float f0 = fmaxf((h ? a10 : a00) + bias, 0.f);
            float f1 = fmaxf((h ? a11 : a01) + bias, 0.f);
            score0 += f0 * em;
            score1 += f1 * em;
        }
    }

    // combine el-parity halves
    score0 += __shfl_xor_sync(0xffffffffu, score0, 16);
    score1 += __shfl_xor_sync(0xffffffffu, score1, 16);

    // weights = softplus(scores @ w3^T + b3)
    float acc0 = b3_s[m], acc1 = acc0;
    #pragma unroll
    for (int m2 = 0; m2 < M_; m2++) {
        float w = w3_s[m * M_ + m2];
        acc0 += w * __shfl_sync(0xffffffffu, score0, (lane & 16) | m2);
        acc1 += w * __shfl_sync(0xffffffffu, score1, (lane & 16) | m2);
    }
    float wg0 = fmaxf(acc0, 0.f) + log1pf(__expf(-fabsf(acc0)));
    float wg1 = fmaxf(acc1, 0.f) + log1pf(__expf(-fabsf(acc1)));

    // L1 normalize over m (16-lane groups)
    float rs0 = wg0, rs1 = wg1;
    #pragma unroll
    for (int off = 8; off; off >>= 1) {
        rs0 += __shfl_xor_sync(0xffffffffu, rs0, off);
        rs1 += __shfl_xor_sync(0xffffffffu, rs1, off);
    }
    float wm0 = wg0 / fmaxf(rs0, 1e-12f);
    float wm1 = wg1 / fmaxf(rs1, 1e-12f);

    // softmax over m
    float mx0 = wm0, mx1 = wm1;
    #pragma unroll
    for (int off = 8; off; off >>= 1) {
        mx0 = fmaxf(mx0, __shfl_xor_sync(0xffffffffu, mx0, off));
        mx1 = fmaxf(mx1, __shfl_xor_sync(0xffffffffu, mx1, off));
    }
    float ex0 = __expf(wm0 - mx0), ex1 = __expf(wm1 - mx1);
    float es0 = ex0, es1 = ex1;
    #pragma unroll
    for (int off = 8; off; off >>= 1) {
        es0 += __shfl_xor_sync(0xffffffffu, es0, off);
        es1 += __shfl_xor_sync(0xffffffffu, es1, off);
    }
    float wmsv[2] = {ex0 / es0, ex1 / es1};
    float wmv [2] = {wm0, wm1};

    if (lane < 16) {
        int lr = 2 * wid;
        #pragma unroll
        for (int r = 0; r < 2; r++) {
            int row = base + lr + r;
            g_wm [row * M_ + m] = wmv[r];
            g_wms[row * M_ + m] = wmsv[r];
            out[O_WMS + row * M_ + m] = wmsv[r];
            wtmp[(lr + r) * M_ + m] = wmv[r];
        }
    }
    __syncthreads();

    if (tid < 16) {
        float v[M_], pw[M_];
        #pragma unroll
        for (int j = 0; j < M_; j++) { v[j] = wtmp[tid * M_ + j]; pw[j] = 0.f; }
        float ssum = 0.f;
        #pragma unroll
        for (int it = 0; it < NL_; it++) {
            int bi = 0; float bv = -1.f;
            #pragma unroll
            for (int j = 0; j < M_; j++) if (v[j] > bv) { bv = v[j]; bi = j; }
            pw[bi] = bv; ssum += bv; v[bi] = -2.f;
        }
        float inv = 1.f / fmaxf(ssum, 1e-12f);
        int row2 = base + tid;
        #pragma unroll
        for (int j = 0; j < M_; j++) g_pw[row2 * M_ + j] = pw[j] * inv;
    }
}

// ---------------------------------------------------------------------------
// Kernel C: 262 MB streamer. One block per row. Models 0-11 via cp.async,
// 12-15 via LDG. NO label logic in the hot loop: ylab fetched directly by
// 16 threads via scattered LDG; slab computed in the epilogue as wm . ylab.
// Final scalar reduce fused via atomic counter (last block).
// ---------------------------------------------------------------------------
__global__ __launch_bounds__(256, 4)
void k_main(const float* __restrict__ y, const int* __restrict__ labels,
            float* __restrict__ out) {
    __shared__ __align__(16) float4 yb_s[12][250];   // 46.9 KB
    __shared__ float wm_sh[M_], pw_sh[M_], ylab[M_];
    __shared__ float red[17][8];
    __shared__ float fin[17];
    __shared__ int islast;

    int b = blockIdx.x, tid = threadIdx.x;
    const float4* yb = (const float4*)(y + (size_t)b * (M_ * C_));
    int lab = __ldg(labels + b);   // broadcast, issued early

    // stage models 0-11 (3 groups of 4) — all issued up front
    #define KSTAGE(q) do {                                                     \
        if (tid < 250) {                                                       \
            _Pragma("unroll")                                                  \
            for (int j_ = 0; j_ < 4; j_++)                                     \
                cp16((uint32_t)__cvta_generic_to_shared(                       \
                         &yb_s[(q) * 4 + j_][tid]),                            \
                     yb + ((q) * 4 + j_) * 250 + tid, 16);                     \
        }                                                                      \
        asm volatile("cp.async.commit_group;\n");                              \
    } while (0)

    KSTAGE(0); KSTAGE(1); KSTAGE(2);

    // models 12-15 via LDG (registers), issued immediately
    float4 va[4];
    if (tid < 250) {
        #pragma unroll
        for (int j = 0; j < 4; j++)
            va[j] = __ldcs(yb + (12 + j) * 250 + tid);
    }

    // label logits fetched directly (replaces all in-loop select logic)
    if (tid < M_) ylab[tid] = __ldg(y + (size_t)b * (M_ * C_) + tid * C_ + lab);

    float my_wms = 0.f;
    if (tid < M_) {
        wm_sh[tid] = g_wm[b * M_ + tid];
        pw_sh[tid] = g_pw[b * M_ + tid];
        my_wms = g_wms[b * M_ + tid];
    }
    __syncthreads();   // publish wm_sh/pw_sh/ylab

    float sume[M_];
    #pragma unroll
    for (int m = 0; m < M_; m++) sume[m] = 0.f;
    float sumS = 0.f;
    float s0 = 0, s1 = 0, s2 = 0, s3 = 0;
    float p0 = 0, p1 = 0, p2 = 0, p3 = 0;

    #define KBODY(m_, v)                                                       \
        do {                                                                   \
            float wm = wm_sh[m_];                                              \
            s0 += wm * v.x; s1 += wm * v.y;                                    \
            s2 += wm * v.z; s3 += wm * v.w;                                    \
            float pw = pw_sh[m_];                                              \
            if (pw != 0.f) {                                                   \
                p0 += pw * v.x; p1 += pw * v.y;                                \
                p2 += pw * v.z; p3 += pw * v.w;                                \
            }                                                                  \
            sume[m_] += __expf(v.x) + __expf(v.y)                              \
                      + __expf(v.z) + __expf(v.w);                             \
        } while (0)

    // register half first (models 12-15)
    if (tid < 250) {
        #pragma unroll
        for (int j = 0; j < 4; j++) KBODY(12 + j, va[j]);
    }

    // smem halves — no barriers: thread reads only its own staged words
    asm volatile("cp.async.wait_group 2;\n");
    if (tid < 250) {
        #pragma unroll
        for (int j = 0; j < 4; j++) { float4 v = yb_s[j][tid]; KBODY(j, v); }
    }
    asm volatile("cp.async.wait_group 1;\n");
    if (tid < 250) {
        #pragma unroll
        for (int j = 4; j < 8; j++) { float4 v = yb_s[j][tid]; KBODY(j, v); }
    }
    asm volatile("cp.async.wait_group 0;\n");
    if (tid < 250) {
        #pragma unroll
        for (int j = 8; j < 12; j++) { float4 v = yb_s[j][tid]; KBODY(j, v); }

        float4* ob = (float4*)(out + O_POST + (size_t)b * C_);
        __stcs(ob + tid, make_float4(p0, p1, p2, p3));
        sumS = __expf(s0) + __expf(s1) + __expf(s2) + __expf(s3);
    }

    // block reduce 17 sums
    int lane = tid & 31, wid = tid >> 5;
    #pragma unroll
    for (int j = 0; j < 17; j++) {
        float v = (j < M_) ? sume[j] : sumS;
        #pragma unroll
        for (int off = 16; off; off >>= 1) v += __shfl_xor_sync(0xffffffffu, v, off);
        if (lane == 0) red[j][wid] = v;
    }
    __syncthreads();
    if (tid < 17) {
        float v = 0.f;
        #pragma unroll
        for (int w = 0; w < 8; w++) v += red[tid][w];
        fin[tid] = v;
    }
    __syncthreads();

    // lane-parallel epilogue (lanes 0-15 of warp 0)
    if (tid < 16) {
        const unsigned msk = 0xffffu;
        float yl  = ylab[tid];
        float lse = __logf(fin[tid]);
        float epl = lse - yl;
        float tcp = __expf(yl - lse);

        float mx = tcp;
        #pragma unroll
        for (int off = 8; off; off >>= 1) mx = fmaxf(mx, __shfl_xor_sync(msk, mx, off));
        float e = __expf(tcp - mx), den = e;
        #pragma unroll
        for (int off = 8; off; off >>= 1) den += __shfl_xor_sync(msk, den, off);
        float tc = e / den;
        out[O_TC + b * M_ + tid] = tc;

        float mx2 = tc;
        #pragma unroll
        for (int off = 8; off; off >>= 1) mx2 = fmaxf(mx2, __shfl_xor_sync(msk, mx2, off));
        float e2 = __expf(tc - mx2), den2 = e2;
        #pragma unroll
        for (int off = 8; off; off >>= 1) den2 += __shfl_xor_sync(msk, den2, off);
        float t = e2 / den2;

        float x = my_wms;
        float conf  = x - x * t + log1pf(__expf(-x));
        float child = epl * x;
        float slabv = wm_sh[tid] * yl;     // s at label = wm . ylab
        #pragma unroll
        for (int off = 8; off; off >>= 1) {
            conf  += __shfl_xor_sync(msk, conf,  off);
            child += __shfl_xor_sync(msk, child, off);
            slabv += __shfl_xor_sync(msk, slabv, off);
        }
        if (tid == 0) {
            g_part[b * 4 + 0] = child;
            g_part[b * 4 + 1] = conf;
            g_part[b * 4 + 2] = __logf(fin[16]) - slabv;
        }
    }
    __syncthreads();

    // fused final reduce: last block to finish sums all partials
    if (tid == 0) {
        __threadfence();
        islast = (atomicAdd(&g_ctr, 1u) == (unsigned)(B_ - 1));
    }
    __syncthreads();
    if (islast) {
        __threadfence();
        float a = 0.f, bb = 0.f, cc = 0.f;
        const float4* gp = (const float4*)g_part;
        for (int i = tid; i < B_; i += 256) {
            float4 r = gp[i];
            a += r.x; bb += r.y; cc += r.z;
        }
        #pragma unroll
        for (int off = 16; off; off >>= 1) {
            a  += __shfl_xor_sync(0xffffffffu, a,  off);
            bb += __shfl_xor_sync(0xffffffffu, bb, off);
            cc += __shfl_xor_sync(0xffffffffu, cc, off);
        }
        if (lane == 0) { red[0][wid] = a; red[1][wid] = bb; red[2][wid] = cc; }
        __syncthreads();
        if (tid == 0) {
            float fa = 0.f, fb = 0.f, fc = 0.f;
            #pragma unroll
            for (int w = 0; w < 8; w++) { fa += red[0][w]; fb += red[1][w]; fc += red[2][w]; }
            out[O_CHILD] = fa / (float)(B_ * M_);
            out[O_CONF]  = fb / (float)(B_ * M_);
            out[O_ENS]   = fc / (float)B_;
        }
    }
}

// ---------------------------------------------------------------------------
extern "C" void kernel_launch(void* const* d_in, const int* in_sizes, int n_in,
                              void* d_out, int out_size) {
    const float* x_in  = (const float*)d_in[0];
    const float* y     = (const float*)d_in[1];
    const int*   labs  = (const int*)  d_in[2];
    const float* memb  = (const float*)d_in[3];
    const float* w1    = (const float*)d_in[4];
    const float* b1    = (const float*)d_in[5];
    const float* w2    = (const float*)d_in[6];
    const float* b2    = (const float*)d_in[7];
    const float* w3    = (const float*)d_in[8];
    const float* b3    = (const float*)d_in[9];
    float* out = (float*)d_out;

    k_emb  <<<dim3(M_, 13), 256>>>(memb, w2, b2);
    k_dummy<<<1, 32>>>();
    k_route<<<B_ / 16, 256>>>(x_in, w1, b1, w3, b3, out);
    k_main <<<B_, 256>>>(y, labs, out);        // profiled (pos 4)
}

// round 8
// speedup vs baseline: 1.0888x; 1.0888x over previous
#include <cuda_runtime.h>
#include <math.h>
#include <stdint.h>

#define B_   4096
#define M_   16
#define C_   1000
#define EMB_ 100
#define EPAD 101
#define K_   1000
#define NL_  4

// output layout (tuple-order concat, fp32)
#define O_POST  0
#define O_CHILD 4096000
#define O_CONF  4096001
#define O_ENS   4096002
#define O_WMS   4096003
#define O_TC    4161539

// scratch
__device__ float g_emb[M_ * EMB_];
__device__ float g_wm [B_ * M_];
__device__ float g_pw [B_ * M_];
__device__ float g_wms[B_ * M_];
__device__ __align__(16) float g_part[B_ * 4];
__device__ unsigned int g_ctr;

__device__ __forceinline__ void cp16(uint32_t d, const void* s, int nbytes) {
    asm volatile("cp.async.cg.shared.global [%0], [%1], 16, %2;\n"
                 :: "r"(d), "l"(s), "r"(nbytes));
}

// ---------------------------------------------------------------------------
// Kernel A: emb[m][e] = relu(model_emb[m,:] . w2[e,:] + b2[e])
// ---------------------------------------------------------------------------
__global__ void k_emb(const float* __restrict__ me, const float* __restrict__ w2,
                      const float* __restrict__ b2) {
    int m = blockIdx.x;
    int wid = threadIdx.x >> 5, lane = threadIdx.x & 31;
    int e = blockIdx.y * 8 + wid;
    if (e >= EMB_) return;
    const float* mer = me + m * K_;
    const float* w2r = w2 + e * K_;
    float acc = 0.f;
    #pragma unroll
    for (int i = 0; i < 32; i++) {
        int k = lane + (i << 5);
        if (k < K_) acc += mer[k] * w2r[k];
    }
    #pragma unroll
    for (int off = 16; off; off >>= 1)
        acc += __shfl_xor_sync(0xffffffffu, acc, off);
    if (lane == 0) g_emb[m * EMB_ + e] = fmaxf(acc + b2[e], 0.f);
}

// resets the completion counter used by k_main's fused final reduce
__global__ void k_dummy() { if (threadIdx.x == 0) g_ctr = 0u; }

// ---------------------------------------------------------------------------
// Kernel B: routing. 256 blocks x 256 threads, 2 rows/warp, 2 CTAs/SM.
// Fold-exchange shuffle reduction: 10 SHFL per el-pair instead of 20.
// ---------------------------------------------------------------------------
#define CE_ 4

__global__ __launch_bounds__(256, 2)
void k_route(const float* __restrict__ x_in, const float* __restrict__ w1,
             const float* __restrict__ b1, const float* __restrict__ w3,
             const float* __restrict__ b3, float* __restrict__ out) {
    __shared__ __align__(16) float w_s[2][CE_ * 1024];   // 32 KB
    __shared__ float emb_s[M_ * EPAD];
    __shared__ float b1_s[EMB_];
    __shared__ float w3_s[M_ * M_];
    __shared__ float b3_s[M_];
    __shared__ float wtmp[16 * M_];

    int tid = threadIdx.x, wid = tid >> 5, lane = tid & 31;
    int base = blockIdx.x * 16;
    int m = lane & 15, h = lane >> 4;

    for (int i = tid; i < M_ * EMB_; i += 256) {
        int mm = i / EMB_, ee = i - mm * EMB_;
        emb_s[mm * EPAD + ee] = g_emb[i];
    }
    if (tid < EMB_) b1_s[tid] = b1[tid];
    if (tid < M_ * M_) w3_s[tid] = w3[tid];
    if (tid < M_) b3_s[tid] = b3[tid];

    // x preload: 2 rows per warp, layout k = 4*lane + 128*i
    float4 xr[2][8];
    #pragma unroll
    for (int r = 0; r < 2; r++) {
        const float* xp = x_in + (size_t)(base + 2 * wid + r) * K_;
        #pragma unroll
        for (int i = 0; i < 8; i++) {
            int k = 4 * lane + 128 * i;
            xr[r][i] = (k < K_) ? *(const float4*)(xp + k)
                                : make_float4(0.f, 0.f, 0.f, 0.f);
        }
    }

    uint32_t wb0 = (uint32_t)__cvta_generic_to_shared(&w_s[0][0]);
    uint32_t wb1 = (uint32_t)__cvta_generic_to_shared(&w_s[1][0]);

    #define STAGE(c, wb) do {                                                  \
        int ec_ = (c) * CE_;                                                   \
        _Pragma("unroll")                                                      \
        for (int j_ = 0; j_ < 4; j_++) {                                       \
            int f4_ = j_ * 256 + tid;                                          \
            int el_ = f4_ >> 8, c4_ = f4_ & 255;                               \
            const float* src_ = w1 + (size_t)(ec_ + el_) * K_                  \
                                  + ((c4_ < 250) ? c4_ * 4 : 0);               \
            int nb_ = (c4_ < 250) ? 16 : 0;                                    \
            cp16((wb) + (uint32_t)((el_ * 1024 + c4_ * 4) * 4), src_, nb_);    \
        }                                                                      \
        asm volatile("cp.async.commit_group;\n");                              \
    } while (0)

    STAGE(0, wb0);

    float score0 = 0.f, score1 = 0.f;

    for (int c = 0; c < 25; c++) {
        asm volatile("cp.async.wait_group 0;\n");
        __syncthreads();
        if (c + 1 < 25) STAGE(c + 1, (c & 1) ? wb0 : wb1);
        const float* wbp = w_s[c & 1];

        #pragma unroll
        for (int ep = 0; ep < 2; ep++) {
            const float* w0p = wbp + (2 * ep) * 1024;
            const float* w1p = wbp + (2 * ep + 1) * 1024;
            float a00 = 0, a01 = 0, a10 = 0, a11 = 0;
            #pragma unroll
            for (int i = 0; i < 8; i++) {
                int k = 4 * lane + 128 * i;
                float4 wa = *(const float4*)(w0p + k);
                float4 wc = *(const float4*)(w1p + k);
                float4 q;
                q = xr[0][i];
                a00 += wa.x*q.x + wa.y*q.y + wa.z*q.z + wa.w*q.w;
                a10 += wc.x*q.x + wc.y*q.y + wc.z*q.z + wc.w*q.w;
                q = xr[1][i];
                a01 += wa.x*q.x + wa.y*q.y + wa.z*q.z + wa.w*q.w;
                a11 += wc.x*q.x + wc.y*q.y + wc.z*q.z + wc.w*q.w;
            }
            // fold-exchange: lower 16 lanes accumulate el0, upper el1
            float y0 = (h ? a10 : a00)
                     + __shfl_xor_sync(0xffffffffu, h ? a00 : a10, 16);
            float y1 = (h ? a11 : a01)
                     + __shfl_xor_sync(0xffffffffu, h ? a01 : a11, 16);
            #pragma unroll
            for (int off = 8; off; off >>= 1) {
                y0 += __shfl_xor_sync(0xffffffffu, y0, off);
                y1 += __shfl_xor_sync(0xffffffffu, y1, off);
            }
            int elh = c * CE_ + 2 * ep + h;
            float bias = b1_s[elh];
            float em   = emb_s[m * EPAD + elh];
            float f0 = fmaxf(y0 + bias, 0.f);
            float f1 = fmaxf(y1 + bias, 0.f);
            score0 += f0 * em;
            score1 += f1 * em;
        }
    }

    // combine el-parity halves
    score0 += __shfl_xor_sync(0xffffffffu, score0, 16);
    score1 += __shfl_xor_sync(0xffffffffu, score1, 16);

    // weights = softplus(scores @ w3^T + b3)
    float acc0 = b3_s[m], acc1 = acc0;
    #pragma unroll
    for (int m2 = 0; m2 < M_; m2++) {
        float w = w3_s[m * M_ + m2];
        acc0 += w * __shfl_sync(0xffffffffu, score0, (lane & 16) | m2);
        acc1 += w * __shfl_sync(0xffffffffu, score1, (lane & 16) | m2);
    }
    float wg0 = fmaxf(acc0, 0.f) + log1pf(__expf(-fabsf(acc0)));
    float wg1 = fmaxf(acc1, 0.f) + log1pf(__expf(-fabsf(acc1)));

    // L1 normalize over m (16-lane groups)
    float rs0 = wg0, rs1 = wg1;
    #pragma unroll
    for (int off = 8; off; off >>= 1) {
        rs0 += __shfl_xor_sync(0xffffffffu, rs0, off);
        rs1 += __shfl_xor_sync(0xffffffffu, rs1, off);
    }
    float wm0 = wg0 / fmaxf(rs0, 1e-12f);
    float wm1 = wg1 / fmaxf(rs1, 1e-12f);

    // softmax over m
    float mx0 = wm0, mx1 = wm1;
    #pragma unroll
    for (int off = 8; off; off >>= 1) {
        mx0 = fmaxf(mx0, __shfl_xor_sync(0xffffffffu, mx0, off));
        mx1 = fmaxf(mx1, __shfl_xor_sync(0xffffffffu, mx1, off));
    }
    float ex0 = __expf(wm0 - mx0), ex1 = __expf(wm1 - mx1);
    float es0 = ex0, es1 = ex1;
    #pragma unroll
    for (int off = 8; off; off >>= 1) {
        es0 += __shfl_xor_sync(0xffffffffu, es0, off);
        es1 += __shfl_xor_sync(0xffffffffu, es1, off);
    }
    float wmsv[2] = {ex0 / es0, ex1 / es1};
    float wmv [2] = {wm0, wm1};

    if (lane < 16) {
        int lr = 2 * wid;
        #pragma unroll
        for (int r = 0; r < 2; r++) {
            int row = base + lr + r;
            g_wm [row * M_ + m] = wmv[r];
            g_wms[row * M_ + m] = wmsv[r];
            out[O_WMS + row * M_ + m] = wmsv[r];
            wtmp[(lr + r) * M_ + m] = wmv[r];
        }
    }
    __syncthreads();

    if (tid < 16) {
        float v[M_], pw[M_];
        #pragma unroll
        for (int j = 0; j < M_; j++) { v[j] = wtmp[tid * M_ + j]; pw[j] = 0.f; }
        float ssum = 0.f;
        #pragma unroll
        for (int it = 0; it < NL_; it++) {
            int bi = 0; float bv = -1.f;
            #pragma unroll
            for (int j = 0; j < M_; j++) if (v[j] > bv) { bv = v[j]; bi = j; }
            pw[bi] = bv; ssum += bv; v[bi] = -2.f;
        }
        float inv = 1.f / fmaxf(ssum, 1e-12f);
        int row2 = base + tid;
        #pragma unroll
        for (int j = 0; j < M_; j++) g_pw[row2 * M_ + j] = pw[j] * inv;
    }
}

// ---------------------------------------------------------------------------
// Kernel C: 262 MB streamer. One block per row. Models 0-11 via cp.async,
// 12-15 via LDG. Label logit held in REGISTERS of threads 0-15 (issued
// early, consumed only in the epilogue — no barrier on its latency).
// Final scalar reduce fused via atomic counter (last block).
// ---------------------------------------------------------------------------
__global__ __launch_bounds__(256, 4)
void k_main(const float* __restrict__ y, const int* __restrict__ labels,
            float* __restrict__ out) {
    __shared__ __align__(16) float4 yb_s[12][250];   // 46.9 KB
    __shared__ float wm_sh[M_], pw_sh[M_];
    __shared__ float red[17][8];
    __shared__ float fin[17];
    __shared__ int islast;

    int b = blockIdx.x, tid = threadIdx.x;
    const float4* yb = (const float4*)(y + (size_t)b * (M_ * C_));

    // stage models 0-11 (3 groups of 4) — all issued up front
    #define KSTAGE(q) do {                                                     \
        if (tid < 250) {                                                       \
            _Pragma("unroll")                                                  \
            for (int j_ = 0; j_ < 4; j_++)                                     \
                cp16((uint32_t)__cvta_generic_to_shared(                       \
                         &yb_s[(q) * 4 + j_][tid]),                            \
                     yb + ((q) * 4 + j_) * 250 + tid, 16);                     \
        }                                                                      \
        asm volatile("cp.async.commit_group;\n");                              \
    } while (0)

    KSTAGE(0); KSTAGE(1); KSTAGE(2);

    // models 12-15 via LDG (registers), issued immediately
    float4 va[4];
    if (tid < 250) {
        #pragma unroll
        for (int j = 0; j < 4; j++)
            va[j] = __ldcs(yb + (12 + j) * 250 + tid);
    }

    // label logit fetched into REGISTER of thread tid (<16); consumed only
    // in the epilogue so the 2-deep LDG chain never gates a barrier.
    float yl_reg = 0.f;
    float my_wms = 0.f;
    if (tid < M_) {
        int lab = __ldg(labels + b);
        yl_reg = __ldg(y + (size_t)b * (M_ * C_) + tid * C_ + lab);
        wm_sh[tid] = g_wm[b * M_ + tid];
        pw_sh[tid] = g_pw[b * M_ + tid];
        my_wms = g_wms[b * M_ + tid];
    }
    __syncthreads();   // publish wm_sh/pw_sh (single-LDG latency only)

    float sume[M_];
    #pragma unroll
    for (int m = 0; m < M_; m++) sume[m] = 0.f;
    float sumS = 0.f;
    float s0 = 0, s1 = 0, s2 = 0, s3 = 0;
    float p0 = 0, p1 = 0, p2 = 0, p3 = 0;

    #define KBODY(m_, v)                                                       \
        do {                                                                   \
            float wm = wm_sh[m_];                                              \
            s0 += wm * v.x; s1 += wm * v.y;                                    \
            s2 += wm * v.z; s3 += wm * v.w;                                    \
            float pw = pw_sh[m_];                                              \
            if (pw != 0.f) {                                                   \
                p0 += pw * v.x; p1 += pw * v.y;                                \
                p2 += pw * v.z; p3 += pw * v.w;                                \
            }                                                                  \
            sume[m_] += __expf(v.x) + __expf(v.y)                              \
                      + __expf(v.z) + __expf(v.w);                             \
        } while (0)

    // register half first (models 12-15)
    if (tid < 250) {
        #pragma unroll
        for (int j = 0; j < 4; j++) KBODY(12 + j, va[j]);
    }

    // smem halves — no barriers: thread reads only its own staged words
    asm volatile("cp.async.wait_group 2;\n");
    if (tid < 250) {
        #pragma unroll
        for (int j = 0; j < 4; j++) { float4 v = yb_s[j][tid]; KBODY(j, v); }
    }
    asm volatile("cp.async.wait_group 1;\n");
    if (tid < 250) {
        #pragma unroll
        for (int j = 4; j < 8; j++) { float4 v = yb_s[j][tid]; KBODY(j, v); }
    }
    asm volatile("cp.async.wait_group 0;\n");
    if (tid < 250) {
        #pragma unroll
        for (int j = 8; j < 12; j++) { float4 v = yb_s[j][tid]; KBODY(j, v); }

        float4* ob = (float4*)(out + O_POST + (size_t)b * C_);
        __stcs(ob + tid, make_float4(p0, p1, p2, p3));
        sumS = __expf(s0) + __expf(s1) + __expf(s2) + __expf(s3);
    }

    // block reduce 17 sums
    int lane = tid & 31, wid = tid >> 5;
    #pragma unroll
    for (int j = 0; j < 17; j++) {
        float v = (j < M_) ? sume[j] : sumS;
        #pragma unroll
        for (int off = 16; off; off >>= 1) v += __shfl_xor_sync(0xffffffffu, v, off);
        if (lane == 0) red[j][wid] = v;
    }
    __syncthreads();
    if (tid < 17) {
        float v = 0.f;
        #pragma unroll
        for (int w = 0; w < 8; w++) v += red[tid][w];
        fin[tid] = v;
    }
    __syncthreads();

    // lane-parallel epilogue (lanes 0-15 of warp 0); yl_reg is thread-local
    if (tid < 16) {
        const unsigned msk = 0xffffu;
        float yl  = yl_reg;
        float lse = __logf(fin[tid]);
        float epl = lse - yl;
        float tcp = __expf(yl - lse);

        float mx = tcp;
        #pragma unroll
        for (int off = 8; off; off >>= 1) mx = fmaxf(mx, __shfl_xor_sync(msk, mx, off));
        float e = __expf(tcp - mx), den = e;
        #pragma unroll
        for (int off = 8; off; off >>= 1) den += __shfl_xor_sync(msk, den, off);
        float tc = e / den;
        out[O_TC + b * M_ + tid] = tc;

        float mx2 = tc;
        #pragma unroll
        for (int off = 8; off; off >>= 1) mx2 = fmaxf(mx2, __shfl_xor_sync(msk, mx2, off));
        float e2 = __expf(tc - mx2), den2 = e2;
        #pragma unroll
        for (int off = 8; off; off >>= 1) den2 += __shfl_xor_sync(msk, den2, off);
        float t = e2 / den2;

        float x = my_wms;
        float conf  = x - x * t + log1pf(__expf(-x));
        float child = epl * x;
        float slabv = wm_sh[tid] * yl;     // ensemble logit at label = wm . ylab
        #pragma unroll
        for (int off = 8; off; off >>= 1) {
            conf  += __shfl_xor_sync(msk, conf,  off);
            child += __shfl_xor_sync(msk, child, off);
            slabv += __shfl_xor_sync(msk, slabv, off);
        }
        if (tid == 0) {
            g_part[b * 4 + 0] = child;
            g_part[b * 4 + 1] = conf;
            g_part[b * 4 + 2] = __logf(fin[16]) - slabv;
        }
    }
    __syncthreads();

    // fused final reduce: last block to finish sums all partials
    if (tid == 0) {
        __threadfence();
        islast = (atomicAdd(&g_ctr, 1u) == (unsigned)(B_ - 1));
    }
    __syncthreads();
    if (islast) {
        __threadfence();
        float a = 0.f, bb = 0.f, cc = 0.f;
        const float4* gp = (const float4*)g_part;
        for (int i = tid; i < B_; i += 256) {
            float4 r = gp[i];
            a += r.x; bb += r.y; cc += r.z;
        }
        #pragma unroll
        for (int off = 16; off; off >>= 1) {
            a  += __shfl_xor_sync(0xffffffffu, a,  off);
            bb += __shfl_xor_sync(0xffffffffu, bb, off);
            cc += __shfl_xor_sync(0xffffffffu, cc, off);
        }
        if (lane == 0) { red[0][wid] = a; red[1][wid] = bb; red[2][wid] = cc; }
        __syncthreads();
        if (tid == 0) {
            float fa = 0.f, fb = 0.f, fc = 0.f;
            #pragma unroll
            for (int w = 0; w < 8; w++) { fa += red[0][w]; fb += red[1][w]; fc += red[2][w]; }
            out[O_CHILD] = fa / (float)(B_ * M_);
            out[O_CONF]  = fb / (float)(B_ * M_);
            out[O_ENS]   = fc / (float)B_;
        }
    }
}

// ---------------------------------------------------------------------------
extern "C" void kernel_launch(void* const* d_in, const int* in_sizes, int n_in,
                              void* d_out, int out_size) {
    const float* x_in  = (const float*)d_in[0];
    const float* y     = (const float*)d_in[1];
    const int*   labs  = (const int*)  d_in[2];
    const float* memb  = (const float*)d_in[3];
    const float* w1    = (const float*)d_in[4];
    const float* b1    = (const float*)d_in[5];
    const float* w2    = (const float*)d_in[6];
    const float* b2    = (const float*)d_in[7];
    const float* w3    = (const float*)d_in[8];
    const float* b3    = (const float*)d_in[9];
    float* out = (float*)d_out;

    k_emb  <<<dim3(M_, 13), 256>>>(memb, w2, b2);
    k_dummy<<<1, 32>>>();
    k_route<<<B_ / 16, 256>>>(x_in, w1, b1, w3, b3, out);
    k_main <<<B_, 256>>>(y, labs, out);        // profiled (pos 4)
}